// round 10
// baseline (speedup 1.0000x reference)
#include <cuda_runtime.h>
#include <cuda_fp16.h>
#include <cstdint>

#define BB 4096
#define TT 512
#define DD 8
#define HH 64
#define TB 32
#define NT 512

// smem byte offsets; all tiles have 256B rows, 16B-chunk XOR swizzle
#define SA0 0        // A0: 32 rows  (k: [x 0..7][1 @8][0 9..15][h0 16..79])  8KB
#define SA1 8192     // A1: 32 rows  (k: [h0 0..63][h1 64..127])              8KB
#define SB0 16384    // B0: 256 rows (k: [Wih0 0..7][b0 @8][0][Whh0 16..79]) 64KB
#define SB1 81920    // B1: 256 rows (k: [Wih1 0..63][Whh1 64..127])         64KB
#define SMEM_TOTAL 147456

static __device__ __forceinline__ uint32_t smem_u32(const void* p){
    uint32_t a;
    asm("{ .reg .u64 t; cvta.to.shared.u64 t, %1; cvt.u32.u64 %0, t; }" : "=r"(a) : "l"(p));
    return a;
}
// swizzled byte offset within a tile: row*256 + (chunk^(row&7)) layout
static __device__ __forceinline__ uint32_t swb(int row, int kb){
    return (uint32_t)(row * 256 + ((((kb) >> 4) ^ (row & 7)) << 4) + ((kb) & 15));
}
static __device__ __forceinline__ float tanha(float x){
    float y; asm("tanh.approx.f32 %0, %1;" : "=f"(y) : "f"(x)); return y;
}
static __device__ __forceinline__ uint32_t pack2(float a, float b){
    __half2 h = __floats2half2_rn(a, b);
    return *(uint32_t*)&h;
}

#define LDSM4(addr, r0, r1, r2, r3) \
    asm volatile("ldmatrix.sync.aligned.m8n8.x4.shared.b16 {%0,%1,%2,%3}, [%4];" \
        : "=r"(r0), "=r"(r1), "=r"(r2), "=r"(r3) : "r"(addr))
#define LDSM2(addr, r0, r1) \
    asm volatile("ldmatrix.sync.aligned.m8n8.x2.shared.b16 {%0,%1}, [%2];" \
        : "=r"(r0), "=r"(r1) : "r"(addr))
#define MMA(accp, ap, b0_, b1_) \
    asm volatile("mma.sync.aligned.m16n8k16.row.col.f32.f16.f16.f32 " \
        "{%0,%1,%2,%3},{%4,%5,%6,%7},{%8,%9},{%0,%1,%2,%3};" \
        : "+f"((accp)[0]), "+f"((accp)[1]), "+f"((accp)[2]), "+f"((accp)[3]) \
        : "r"((ap)[0]), "r"((ap)[1]), "r"((ap)[2]), "r"((ap)[3]), "r"(b0_), "r"(b1_))

// warp computes z-tile [16 rows x 32 cols] = A[m0..+15, :] @ B[nbase..+31, :]^T
template<int KTILES>
static __device__ __forceinline__ void gemm_tile(uint32_t abase, uint32_t bbase,
                                                 int m0, int nbase, int lane,
                                                 float acc[4][4])
{
    const int amat = lane >> 3;
    const int arow = m0 + (lane & 7) + (amat & 1) * 8;
    const uint32_t arb = abase + (uint32_t)(arow * 256);
    const int arx = arow & 7;
    const int apc = amat >> 1;
    uint32_t af[KTILES][4];
    #pragma unroll
    for (int kt = 0; kt < KTILES; kt++) {
        uint32_t ad = arb + (uint32_t)(((2 * kt + apc) ^ arx) << 4);
        LDSM4(ad, af[kt][0], af[kt][1], af[kt][2], af[kt][3]);
    }
    const int bl  = lane & 7;
    const int bco = lane >> 3;
    #pragma unroll
    for (int nt = 0; nt < 4; nt++) {
        const int brow = nbase + 8 * nt + bl;
        const uint32_t brb = bbase + (uint32_t)(brow * 256);
        const int brx = brow & 7;
        #pragma unroll
        for (int ktp = 0; ktp < KTILES / 2; ktp++) {
            uint32_t b0, b1, b2, b3;
            uint32_t bd = brb + (uint32_t)(((4 * ktp + bco) ^ brx) << 4);
            LDSM4(bd, b0, b1, b2, b3);
            MMA(acc[nt], af[2 * ktp],     b0, b1);
            MMA(acc[nt], af[2 * ktp + 1], b2, b3);
        }
        if (KTILES & 1) {
            const int kt = KTILES - 1;
            uint32_t b0, b1;
            uint32_t bd = brb + (uint32_t)(((2 * kt + (bco & 1)) ^ brx) << 4);
            LDSM2(bd, b0, b1);
            MMA(acc[nt], af[kt], b0, b1);
        }
    }
}

// column permutation (32-col period): n = 32*nb + 8*s + 2*cc + e
//   unit u = 8*nb + 4*(s&1) + cc,  gate g = 2*(s>>1) + e
static __device__ __forceinline__ void decode_n(int n, int& u, int& g){
    int nb = n >> 5, s = (n >> 3) & 3, cc = (n >> 1) & 3, e = n & 1;
    u = 8 * nb + 4 * (s & 1) + cc;
    g = 2 * (s >> 1) + e;
}

__global__ void __launch_bounds__(NT, 1)
lstm_mma(const float* __restrict__ x,
         const float* __restrict__ Wih0, const float* __restrict__ Whh0,
         const float* __restrict__ bih0, const float* __restrict__ bhh0,
         const float* __restrict__ Wih1, const float* __restrict__ Whh1,
         const float* __restrict__ bih1, const float* __restrict__ bhh1,
         const float* __restrict__ Wfc,  const float* __restrict__ bfc,
         float* __restrict__ out)
{
    extern __shared__ char sm[];
    const uint32_t sbase = smem_u32(sm);
    const int tid = threadIdx.x, lane = tid & 31, w = tid >> 5;
    const int r = lane >> 2, cc = lane & 3;
    const int m0 = 16 * (w & 1);         // M tile rows
    const int nb = w >> 1;               // 32-col block (0..7)
    const int U0 = 8 * nb;               // unit base
    const int nbase = 32 * nb;           // B row base
    const int b0g = blockIdx.x * TB;

    // zero A0 + A1
    for (int i = tid; i < 1024; i += NT) ((uint4*)sm)[i] = make_uint4(0, 0, 0, 0);

    // B0: [Wih0 | b0 | 0 | Whh0], permuted rows, swizzled
    for (int idx = tid; idx < 256 * 128; idx += NT) {
        int n = idx >> 7, k = idx & 127;
        int u, g; decode_n(n, u, g);
        int sr = g * 64 + u;
        float v = 0.f;
        if (k < 8)            v = Wih0[sr * DD + k];
        else if (k == 8)      v = bih0[sr] + bhh0[sr];
        else if (k >= 16 && k < 80) v = Whh0[sr * HH + (k - 16)];
        *(__half*)(sm + SB0 + swb(n, 2 * k)) = __float2half_rn(v);
    }
    // B1: [Wih1 | Whh1]
    for (int idx = tid; idx < 256 * 128; idx += NT) {
        int n = idx >> 7, k = idx & 127;
        int u, g; decode_n(n, u, g);
        int sr = g * 64 + u;
        float v = (k < 64) ? Wih1[sr * HH + k] : Whh1[sr * HH + (k - 64)];
        *(__half*)(sm + SB1 + swb(n, 2 * k)) = __float2half_rn(v);
    }

    // bias1 in regs (0.5-prescaled for sigmoid gates), 2 units per thread
    float bi05[2], bf05[2], bg1[2], bo05[2];
    #pragma unroll
    for (int j = 0; j < 2; j++) {
        int u = U0 + 4 * j + cc;
        bi05[j] = 0.5f * (bih1[u]       + bhh1[u]);
        bf05[j] = 0.5f * (bih1[64 + u]  + bhh1[64 + u]);
        bg1[j]  =        (bih1[128 + u] + bhh1[128 + u]);
        bo05[j] = 0.5f * (bih1[192 + u] + bhh1[192 + u]);
    }
    __syncthreads();

    // A0 const-1 column (k=8) + x_0
    if (tid < TB) {
        *(__half*)(sm + SA0 + swb(tid, 16)) = __float2half_rn(1.0f);
        const float* xp = x + (size_t)(b0g + tid) * TT * DD;
        float4 xa = ((const float4*)xp)[0], xb = ((const float4*)xp)[1];
        uint4 v;
        v.x = pack2(xa.x, xa.y); v.y = pack2(xa.z, xa.w);
        v.z = pack2(xb.x, xb.y); v.w = pack2(xb.z, xb.w);
        *(uint4*)(sm + SA0 + (uint32_t)(tid * 256 + ((tid & 7) << 4))) = v;
    }
    __syncthreads();

    float c0s[4], c1s[4];
    #pragma unroll
    for (int i = 0; i < 4; i++) { c0s[i] = 0.f; c1s[i] = 0.f; }
    float acc[4][4];

    for (int t = 0; t < TT; t++) {
        // prefetch x_{t+1}
        float4 xa, xb;
        const bool hx = (tid < TB) && (t + 1 < TT);
        if (hx) {
            const float* xp = x + (size_t)(b0g + tid) * TT * DD + (size_t)(t + 1) * DD;
            xa = ((const float4*)xp)[0]; xb = ((const float4*)xp)[1];
        }

        // ---- layer 0: z0 = [x|1|h0] @ B0^T ----
        #pragma unroll
        for (int nt = 0; nt < 4; nt++)
            { acc[nt][0] = 0.f; acc[nt][1] = 0.f; acc[nt][2] = 0.f; acc[nt][3] = 0.f; }
        gemm_tile<5>(sbase + SA0, sbase + SB0, m0, nbase, lane, acc);
        __syncthreads();

        if (hx) {
            uint4 v;
            v.x = pack2(xa.x, xa.y); v.y = pack2(xa.z, xa.w);
            v.z = pack2(xb.x, xb.y); v.w = pack2(xb.z, xb.w);
            *(uint4*)(sm + SA0 + (uint32_t)(tid * 256 + ((tid & 7) << 4))) = v;
        }
        // epilogue 0: 4 cells/thread (units U0+cc, U0+4+cc; rows r, r+8)
        #pragma unroll
        for (int j = 0; j < 2; j++) {
            #pragma unroll
            for (int rh = 0; rh < 2; rh++) {
                float zi = acc[j][rh * 2],     zf = acc[j][rh * 2 + 1];
                float zg = acc[2 + j][rh * 2], zo = acc[2 + j][rh * 2 + 1];
                float I = 0.5f * tanha(0.5f * zi) + 0.5f;
                float F = 0.5f * tanha(0.5f * zf) + 0.5f;
                float G = tanha(zg);
                float O = 0.5f * tanha(0.5f * zo) + 0.5f;
                int ci = j * 2 + rh;
                float cn = F * c0s[ci] + I * G;
                c0s[ci] = cn;
                float h = O * tanha(cn);
                int u = U0 + 4 * j + cc;
                int row = m0 + r + rh * 8;
                __half hh = __float2half_rn(h);
                *(__half*)(sm + SA0 + swb(row, 2 * (16 + u))) = hh;  // layer-0 recurrence
                *(__half*)(sm + SA1 + swb(row, 2 * u)) = hh;         // layer-1 input
            }
        }
        __syncthreads();

        // ---- layer 1: z1 = [h0|h1] @ B1^T ----
        #pragma unroll
        for (int nt = 0; nt < 4; nt++)
            { acc[nt][0] = 0.f; acc[nt][1] = 0.f; acc[nt][2] = 0.f; acc[nt][3] = 0.f; }
        gemm_tile<8>(sbase + SA1, sbase + SB1, m0, nbase, lane, acc);
        __syncthreads();

        // epilogue 1 (bias1 added here)
        #pragma unroll
        for (int j = 0; j < 2; j++) {
            #pragma unroll
            for (int rh = 0; rh < 2; rh++) {
                float zi = acc[j][rh * 2],     zf = acc[j][rh * 2 + 1];
                float zg = acc[2 + j][rh * 2], zo = acc[2 + j][rh * 2 + 1];
                float I = 0.5f * tanha(0.5f * zi + bi05[j]) + 0.5f;
                float F = 0.5f * tanha(0.5f * zf + bf05[j]) + 0.5f;
                float G = tanha(zg + bg1[j]);
                float O = 0.5f * tanha(0.5f * zo + bo05[j]) + 0.5f;
                int ci = j * 2 + rh;
                float cn = F * c1s[ci] + I * G;
                c1s[ci] = cn;
                float h = O * tanha(cn);
                int u = U0 + 4 * j + cc;
                int row = m0 + r + rh * 8;
                *(__half*)(sm + SA1 + swb(row, 2 * (64 + u))) = __float2half_rn(h);
            }
        }
        // epilogue-1 writes ordered before next gemm1 by the sync after next gemm0
    }

    __syncthreads();
    // final FC: out[b] = h1_last . Wfc + bfc
    if (tid < TB) {
        float s = bfc[0];
        #pragma unroll 8
        for (int u = 0; u < HH; u++)
            s += __half2float(*(const __half*)(sm + SA1 + swb(tid, 2 * (64 + u)))) * Wfc[u];
        out[b0g + tid] = s;
    }
}

extern "C" void kernel_launch(void* const* d_in, const int* in_sizes, int n_in,
                              void* d_out, int out_size)
{
    (void)in_sizes; (void)n_in; (void)out_size;
    cudaFuncSetAttribute(lstm_mma, cudaFuncAttributeMaxDynamicSharedMemorySize, SMEM_TOTAL);
    lstm_mma<<<BB / TB, NT, SMEM_TOTAL>>>(
        (const float*)d_in[0],
        (const float*)d_in[1], (const float*)d_in[2],
        (const float*)d_in[3], (const float*)d_in[4],
        (const float*)d_in[5], (const float*)d_in[6],
        (const float*)d_in[7], (const float*)d_in[8],
        (const float*)d_in[9], (const float*)d_in[10],
        (float*)d_out);
}

// round 11
// speedup vs baseline: 1.3925x; 1.3925x over previous
#include <cuda_runtime.h>
#include <cuda_fp16.h>
#include <cstdint>

#define BB 4096
#define TT 512
#define DD 8
#define HH 64
#define TB 32
#define NT 512

// smem layout: B0, B1 weight tiles + double-buffered A operands (256B rows, XOR-16B swizzle)
#define SB0 0            // B0: 256 rows (k: [Wih0 0..7][b0 @8][0][Whh0 16..79][0..])  64KB
#define SB1 65536        // B1: 256 rows (k: [Wih1 0..63][Whh1 64..127])               64KB
#define SA0P(p) (131072 + (p) * 8192)  // A0 bufs: 32 rows (k: [x|1|pad|h0])
#define SA1P(p) (147456 + (p) * 8192)  // A1 bufs: 32 rows (k: [h0|h1])
#define SMEM_TOTAL 163840

static __device__ __forceinline__ uint32_t smem_u32(const void* p){
    uint32_t a;
    asm("{ .reg .u64 t; cvta.to.shared.u64 t, %1; cvt.u32.u64 %0, t; }" : "=r"(a) : "l"(p));
    return a;
}
static __device__ __forceinline__ uint32_t swb(int row, int kb){
    return (uint32_t)(row * 256 + ((((kb) >> 4) ^ (row & 7)) << 4) + ((kb) & 15));
}
static __device__ __forceinline__ float tanha(float x){
    float y; asm("tanh.approx.f32 %0, %1;" : "=f"(y) : "f"(x)); return y;
}
static __device__ __forceinline__ uint32_t pack2(float a, float b){
    __half2 h = __floats2half2_rn(a, b);
    return *(uint32_t*)&h;
}

#define LDSM4(addr, r0, r1, r2, r3) \
    asm volatile("ldmatrix.sync.aligned.m8n8.x4.shared.b16 {%0,%1,%2,%3}, [%4];" \
        : "=r"(r0), "=r"(r1), "=r"(r2), "=r"(r3) : "r"(addr))
#define LDSM2(addr, r0, r1) \
    asm volatile("ldmatrix.sync.aligned.m8n8.x2.shared.b16 {%0,%1}, [%2];" \
        : "=r"(r0), "=r"(r1) : "r"(addr))
#define MMA(accp, ap, b0_, b1_) \
    asm volatile("mma.sync.aligned.m16n8k16.row.col.f32.f16.f16.f32 " \
        "{%0,%1,%2,%3},{%4,%5,%6,%7},{%8,%9},{%0,%1,%2,%3};" \
        : "+f"((accp)[0]), "+f"((accp)[1]), "+f"((accp)[2]), "+f"((accp)[3]) \
        : "r"((ap)[0]), "r"((ap)[1]), "r"((ap)[2]), "r"((ap)[3]), "r"(b0_), "r"(b1_))

// warp computes z-tile [16 rows x 64 cols] = A[m0..+15, :] @ B[nbase..+63, :]^T
template<int KTILES>
static __device__ __forceinline__ void gemm_tile(uint32_t abase, uint32_t bbase,
                                                 int m0, int nbase, int lane,
                                                 float acc[8][4])
{
    const int amat = lane >> 3;
    const int arow = m0 + (lane & 7) + (amat & 1) * 8;
    const uint32_t arb = abase + (uint32_t)(arow * 256);
    const int arx = arow & 7;
    const int apc = amat >> 1;
    uint32_t af[KTILES][4];
    #pragma unroll
    for (int kt = 0; kt < KTILES; kt++) {
        uint32_t ad = arb + (uint32_t)(((2 * kt + apc) ^ arx) << 4);
        LDSM4(ad, af[kt][0], af[kt][1], af[kt][2], af[kt][3]);
    }
    const int bl  = lane & 7;
    const int bco = lane >> 3;
    #pragma unroll
    for (int nt = 0; nt < 8; nt++) {
        const int brow = nbase + 8 * nt + bl;
        const uint32_t brb = bbase + (uint32_t)(brow * 256);
        const int brx = brow & 7;
        #pragma unroll
        for (int ktp = 0; ktp < KTILES / 2; ktp++) {
            uint32_t b0, b1, b2, b3;
            uint32_t bd = brb + (uint32_t)(((4 * ktp + bco) ^ brx) << 4);
            LDSM4(bd, b0, b1, b2, b3);
            MMA(acc[nt], af[2 * ktp],     b0, b1);
            MMA(acc[nt], af[2 * ktp + 1], b2, b3);
        }
        if (KTILES & 1) {
            const int kt = KTILES - 1;
            uint32_t b0, b1;
            uint32_t bd = brb + (uint32_t)(((2 * kt + (bco & 1)) ^ brx) << 4);
            LDSM2(bd, b0, b1);
            MMA(acc[nt], af[kt], b0, b1);
        }
    }
}

// column permutation (64-col period): n = 64*blk + 32*gp + 8*j + pos
//   u = 16*blk + 4*j + (pos>>1),  g = 2*gp + (pos&1)
static __device__ __forceinline__ void decode_n(int n, int& u, int& g){
    int blk = n >> 6, w64 = n & 63;
    int gp = w64 >> 5, rem = w64 & 31;
    int j = rem >> 3, pos = rem & 7;
    u = (blk << 4) + (j << 2) + (pos >> 1);
    g = (gp << 1) + (pos & 1);
}

__global__ void __launch_bounds__(NT, 1)
lstm_mma(const float* __restrict__ x,
         const float* __restrict__ Wih0, const float* __restrict__ Whh0,
         const float* __restrict__ bih0, const float* __restrict__ bhh0,
         const float* __restrict__ Wih1, const float* __restrict__ Whh1,
         const float* __restrict__ bih1, const float* __restrict__ bhh1,
         const float* __restrict__ Wfc,  const float* __restrict__ bfc,
         float* __restrict__ out)
{
    extern __shared__ char sm[];
    const uint32_t sbase = smem_u32(sm);
    const int tid = threadIdx.x, lane = tid & 31, w = tid >> 5;
    const int r = lane >> 2, cc = lane & 3;
    const bool isL0 = (w < 8);
    const int wl = isL0 ? w : (w - 8);
    const int m0 = 16 * (wl & 1);   // M tile rows
    const int q  = wl >> 1;         // 64-col block (0..3)
    const int U0 = 16 * q;          // unit base
    const int nbase = 64 * q;       // B row base
    const int b0g = blockIdx.x * TB;

    // zero all 4 A buffers (32KB)
    for (int i = tid; i < 2048; i += NT)
        ((uint4*)(sm + SA0P(0)))[i] = make_uint4(0, 0, 0, 0);

    // B0: [Wih0 | b0 | 0 | Whh0 | 0], permuted rows, swizzled
    for (int idx = tid; idx < 256 * 128; idx += NT) {
        int n = idx >> 7, k = idx & 127;
        int u, g; decode_n(n, u, g);
        int sr = g * 64 + u;
        float v = 0.f;
        if (k < 8)                  v = Wih0[sr * DD + k];
        else if (k == 8)            v = bih0[sr] + bhh0[sr];
        else if (k >= 16 && k < 80) v = Whh0[sr * HH + (k - 16)];
        *(__half*)(sm + SB0 + swb(n, 2 * k)) = __float2half_rn(v);
    }
    // B1: [Wih1 | Whh1]
    for (int idx = tid; idx < 256 * 128; idx += NT) {
        int n = idx >> 7, k = idx & 127;
        int u, g; decode_n(n, u, g);
        int sr = g * 64 + u;
        float v = (k < 64) ? Wih1[sr * HH + k] : Whh1[sr * HH + (k - 64)];
        *(__half*)(sm + SB1 + swb(n, 2 * k)) = __float2half_rn(v);
    }

    // bias1 in regs (0.5-prescaled for sigmoid gates) — L1 warps only
    float bi05[4], bf05[4], bg1[4], bo05[4];
    if (!isL0) {
        #pragma unroll
        for (int j = 0; j < 4; j++) {
            int u = U0 + 4 * j + cc;
            bi05[j] = 0.5f * (bih1[u]       + bhh1[u]);
            bf05[j] = 0.5f * (bih1[64 + u]  + bhh1[64 + u]);
            bg1[j]  =        (bih1[128 + u] + bhh1[128 + u]);
            bo05[j] = 0.5f * (bih1[192 + u] + bhh1[192 + u]);
        }
    }
    __syncthreads();

    // const-1 column (k=8) in BOTH A0 buffers + x_0 into A0 buf 0
    if (tid < TB) {
        *(__half*)(sm + SA0P(0) + swb(tid, 16)) = __float2half_rn(1.0f);
        *(__half*)(sm + SA0P(1) + swb(tid, 16)) = __float2half_rn(1.0f);
        const float* xp = x + (size_t)(b0g + tid) * TT * DD;
        float4 xa = ((const float4*)xp)[0], xb = ((const float4*)xp)[1];
        uint4 v;
        v.x = pack2(xa.x, xa.y); v.y = pack2(xa.z, xa.w);
        v.z = pack2(xb.x, xb.y); v.w = pack2(xb.z, xb.w);
        *(uint4*)(sm + SA0P(0) + (uint32_t)(tid * 256 + ((tid & 7) << 4))) = v;
    }
    __syncthreads();

    float cs[8];
    #pragma unroll
    for (int i = 0; i < 8; i++) cs[i] = 0.f;
    float acc[8][4];
    float4 xa, xb;

    // Pipelined: L0 computes step i, L1 computes step i-1 (epilogue at i-2).
    for (int i = 0; i <= TT + 1; i++) {
        const int pA = i & 1;

        // ---------- phase A: L0 gemm(step i)  ||  L1 epilogue(step i-2) ----------
        if (isL0) {
            if (i < TT) {
                if (w == 0 && i + 1 < TT) {   // prefetch x_{i+1}, hidden under gemm
                    const float* xp = x + (size_t)(b0g + lane) * TT * DD + (size_t)(i + 1) * DD;
                    xa = ((const float4*)xp)[0]; xb = ((const float4*)xp)[1];
                }
                #pragma unroll
                for (int nt = 0; nt < 8; nt++)
                    { acc[nt][0] = 0.f; acc[nt][1] = 0.f; acc[nt][2] = 0.f; acc[nt][3] = 0.f; }
                gemm_tile<5>(sbase + SA0P(pA), sbase + SB0, m0, nbase, lane, acc);
            }
        } else {
            if (i >= 2) {
                const uint32_t dstH1 = sbase + SA1P((i - 1) & 1);
                #pragma unroll
                for (int j = 0; j < 4; j++) {
                    #pragma unroll
                    for (int rh = 0; rh < 2; rh++) {
                        float zi = acc[j][rh * 2],     zf = acc[j][rh * 2 + 1];
                        float zg = acc[4 + j][rh * 2], zo = acc[4 + j][rh * 2 + 1];
                        float I = 0.5f * tanha(0.5f * zi + bi05[j]) + 0.5f;
                        float F = 0.5f * tanha(0.5f * zf + bf05[j]) + 0.5f;
                        float G = tanha(zg + bg1[j]);
                        float O = 0.5f * tanha(0.5f * zo + bo05[j]) + 0.5f;
                        int ci = j * 2 + rh;
                        float cn = F * cs[ci] + I * G;
                        cs[ci] = cn;
                        float h = O * tanha(cn);
                        int u = U0 + 4 * j + cc;
                        int row = m0 + r + rh * 8;
                        *(__half*)(sm + ((i - 1) & 1) * 0 + 0 + (dstH1 - sbase) + swb(row, 2 * (64 + u))) = __float2half_rn(h);
                    }
                }
            }
        }
        __syncthreads();

        // ---------- phase B: L0 epilogue(step i)  ||  L1 gemm(step i-1) ----------
        if (isL0) {
            if (i < TT) {
                if (w == 0 && i + 1 < TT) {
                    uint4 v;
                    v.x = pack2(xa.x, xa.y); v.y = pack2(xa.z, xa.w);
                    v.z = pack2(xb.x, xb.y); v.w = pack2(xb.z, xb.w);
                    *(uint4*)(sm + SA0P(pA ^ 1) + (uint32_t)(lane * 256 + ((lane & 7) << 4))) = v;
                }
                const uint32_t dstA0 = sbase + SA0P(pA ^ 1);
                const uint32_t dstA1 = sbase + SA1P(pA);
                #pragma unroll
                for (int j = 0; j < 4; j++) {
                    #pragma unroll
                    for (int rh = 0; rh < 2; rh++) {
                        float zi = acc[j][rh * 2],     zf = acc[j][rh * 2 + 1];
                        float zg = acc[4 + j][rh * 2], zo = acc[4 + j][rh * 2 + 1];
                        float I = 0.5f * tanha(0.5f * zi) + 0.5f;
                        float F = 0.5f * tanha(0.5f * zf) + 0.5f;
                        float G = tanha(zg);
                        float O = 0.5f * tanha(0.5f * zo) + 0.5f;
                        int ci = j * 2 + rh;
                        float cn = F * cs[ci] + I * G;
                        cs[ci] = cn;
                        float h = O * tanha(cn);
                        int u = U0 + 4 * j + cc;
                        int row = m0 + r + rh * 8;
                        __half hh = __float2half_rn(h);
                        *(__half*)(sm + (dstA0 - sbase) + swb(row, 2 * (16 + u))) = hh;  // L0 recurrence
                        *(__half*)(sm + (dstA1 - sbase) + swb(row, 2 * u)) = hh;         // L1 input
                    }
                }
            }
        } else {
            if (i >= 1 && i <= TT) {
                #pragma unroll
                for (int nt = 0; nt < 8; nt++)
                    { acc[nt][0] = 0.f; acc[nt][1] = 0.f; acc[nt][2] = 0.f; acc[nt][3] = 0.f; }
                gemm_tile<8>(sbase + SA1P((i - 1) & 1), sbase + SB1, m0, nbase, lane, acc);
            }
        }
        __syncthreads();
    }

    // final FC: h1_{511} lives in A1 buf[0] (k 64..127)
    if (tid < TB) {
        float s = bfc[0];
        #pragma unroll 8
        for (int u = 0; u < HH; u++)
            s += __half2float(*(const __half*)(sm + SA1P(0) + swb(tid, 2 * (64 + u)))) * Wfc[u];
        out[b0g + tid] = s;
    }
}

extern "C" void kernel_launch(void* const* d_in, const int* in_sizes, int n_in,
                              void* d_out, int out_size)
{
    (void)in_sizes; (void)n_in; (void)out_size;
    cudaFuncSetAttribute(lstm_mma, cudaFuncAttributeMaxDynamicSharedMemorySize, SMEM_TOTAL);
    lstm_mma<<<BB / TB, NT, SMEM_TOTAL>>>(
        (const float*)d_in[0],
        (const float*)d_in[1], (const float*)d_in[2],
        (const float*)d_in[3], (const float*)d_in[4],
        (const float*)d_in[5], (const float*)d_in[6],
        (const float*)d_in[7], (const float*)d_in[8],
        (const float*)d_in[9], (const float*)d_in[10],
        (float*)d_out);
}